// round 9
// baseline (speedup 1.0000x reference)
#include <cuda_runtime.h>

#define HH 256
#define WW 256
#define NW 8                 // 256 cols / 32
#define NPIX (8 * HH * WW)   // mean denominator
#define NBLK 512             // 64 bands x 8 batch
#define BAND 4               // core rows per block
#define WROWS 10             // window rows = BAND + 2*3

__device__ float    g_accum = 0.0f;
__device__ unsigned g_done  = 0u;

// scale LUT: level idx 0..7 -> r^2 in {1,2,4,5,8,9,10,13}, packed nibbles
#define SCALE_LUT 0xDA985421u

// ---------------------------------------------------------------------------
// Exact fallback: expanding float-based scan for nearest opposite-class pixel.
// Reached only when no opposite pixel lies within r^2 <= 13 (prob ~1e-4 of
// ANY event in this input). Exact for all inputs; 1e20 if none exists.
// ---------------------------------------------------------------------------
__device__ __noinline__ float slow_scan(const float* __restrict__ im, int i, int j, bool cls) {
    float best = 1e20f;
    for (int dd = 0; dd < HH; ++dd) {
        float dd2 = (float)(dd * dd);
        if (dd2 >= best) break;
#pragma unroll 1
        for (int s2 = 0; s2 < 2; ++s2) {
            if (s2 && dd == 0) continue;
            int r = s2 ? i - dd : i + dd;
            if (r < 0 || r >= HH) continue;
            const float* row = im + (size_t)r * WW;
            for (int dj = 0; dj < WW; ++dj) {
                float tot = dd2 + (float)(dj * dj);
                if (tot >= best) break;
                int c1 = j + dj, c2 = j - dj;
                if (c1 < WW && ((row[c1] > 0.5f) != cls)) { best = tot; break; }
                if (dj && c2 >= 0 && ((row[c2] > 0.5f) != cls)) { best = tot; break; }
            }
        }
    }
    return best;
}

// ---------------------------------------------------------------------------
// Single fused kernel. Block = (band of 4 rows, batch), 256 threads (8 warps).
// Phase 0: slot = (window row, word); warp loads pred+target, ballots masks
//          into shared, stages w = (p-t)^2 for core rows.
// Phase 1: ALL 8 warps: warp-pair = level-pair, lane = (image,row,word) task.
//          8 independent hit masks per word (r^2 = 1,2,4,5,8,9,10,13), no
//          priority chain (resolved per-lane in phase 2 by ffs order).
// Phase 2: warp = (row, word-half), lane = pixel: v = 8 level bits;
//          s = nibble-LUT[ffs(v)]; acc += w*(s_pred+s_target); v==0 -> exact.
// Output: last-block finalize (idempotent across graph replays).
// ---------------------------------------------------------------------------
__global__ void __launch_bounds__(256) hd_loss_kernel(const float* __restrict__ pred,
                                                      const float* __restrict__ target,
                                                      float* __restrict__ out) {
    int band = blockIdx.x;          // 0..63
    int b    = blockIdx.y;          // 0..7
    int tid  = threadIdx.x;         // 0..255
    int lane = tid & 31;
    int warp = tid >> 5;            // 0..7

    __shared__ unsigned SM[2][WROWS][10];    // window rows band*4-3..+6, pad cols 0,9
    __shared__ uint2    SL[2][BAND][NW][4];  // 8 level masks per (img,row,word)
    __shared__ float    w_sh[BAND][WW];      // (p-t)^2 core rows
    __shared__ float    sred[8];

    const float* pbase = pred   + (size_t)b * HH * WW;
    const float* tbase = target + (size_t)b * HH * WW;

    // zero pads: 2 img x 10 rows x 2 pad cols = 40 slots
    if (tid < 40) {
        int f = tid / 20, rr = (tid >> 1) % 10, cc = tid & 1;
        SM[f][rr][cc * 9] = 0u;
    }

    // ---------------- Phase 0: loads + ballots + w staging ----------------
#pragma unroll
    for (int k = 0; k < 10; ++k) {
        int s  = warp + k * 8;      // 0..79
        int rr = s >> 3;            // window row 0..9
        int ww = s & 7;
        int gi = band * BAND - 3 + rr;
        gi = gi < 0 ? 0 : (gi > HH - 1 ? HH - 1 : gi);   // clamped; rv masks fix validity
        float vp = pbase[(size_t)gi * WW + ww * 32 + lane];
        float vt = tbase[(size_t)gi * WW + ww * 32 + lane];
        unsigned mp = __ballot_sync(0xFFFFFFFFu, vp > 0.5f);
        unsigned mt = __ballot_sync(0xFFFFFFFFu, vt > 0.5f);
        if (lane == 0) {
            SM[0][rr][ww + 1] = mp;
            SM[1][rr][ww + 1] = mt;
        }
        if (rr >= 3 && rr < 3 + BAND) {
            float d = vp - vt;
            w_sh[rr - 3][ww * 32 + lane] = d * d;
        }
    }
    __syncthreads();

    // ---------------- Phase 1: 8 warps x 64 tasks, level-pair per warp-pair ----------------
    {
        int sub  = warp >> 1;        // 0..3 (uniform per warp)
        int task = tid & 63;         // (image, row, word)
        int f1 = task >> 5;
        int rr = (task >> 3) & 3;
        int w1 = task & 7;
        int i1 = band * BAND + rr;
        int sr = rr + 3;
        const unsigned (*M)[10] = SM[f1];

        unsigned W  = M[sr][w1 + 1];
        unsigned l0 = M[sr][w1], r0 = M[sr][w1 + 2];

        unsigned mlo1 = (w1 == 0) ? 0xFFFFFFFEu : 0xFFFFFFFFu;
        unsigned mlo2 = (w1 == 0) ? 0xFFFFFFFCu : 0xFFFFFFFFu;
        unsigned mlo3 = (w1 == 0) ? 0xFFFFFFF8u : 0xFFFFFFFFu;
        unsigned mhi1 = (w1 == 7) ? 0x7FFFFFFFu : 0xFFFFFFFFu;
        unsigned mhi2 = (w1 == 7) ? 0x3FFFFFFFu : 0xFFFFFFFFu;
        unsigned mhi3 = (w1 == 7) ? 0x1FFFFFFFu : 0xFFFFFFFFu;
        unsigned rvU1 = (i1 >= 1)      ? 0xFFFFFFFFu : 0u;
        unsigned rvD1 = (i1 <= HH - 2) ? 0xFFFFFFFFu : 0u;
        unsigned rvU2 = (i1 >= 2)      ? 0xFFFFFFFFu : 0u;
        unsigned rvD2 = (i1 <= HH - 3) ? 0xFFFFFFFFu : 0u;
        unsigned rvU3 = (i1 >= 3)      ? 0xFFFFFFFFu : 0u;
        unsigned rvD3 = (i1 <= HH - 4) ? 0xFFFFFFFFu : 0u;

        uint2 res;
        if (sub == 0) {
            unsigned cU1 = M[sr - 1][w1 + 1], lU1 = M[sr - 1][w1], rU1 = M[sr - 1][w1 + 2];
            unsigned cD1 = M[sr + 1][w1 + 1], lD1 = M[sr + 1][w1], rD1 = M[sr + 1][w1 + 2];
            // s=1: (0,+-1), (+-1,0)
            unsigned h1 = ((W ^ __funnelshift_l(l0, W, 1)) & mlo1)
                        | ((W ^ __funnelshift_r(W, r0, 1)) & mhi1)
                        | ((W ^ cU1) & rvU1) | ((W ^ cD1) & rvD1);
            // s=2: (+-1,+-1)
            unsigned h2 = ((((W ^ __funnelshift_l(lU1, cU1, 1)) & mlo1)
                          | ((W ^ __funnelshift_r(cU1, rU1, 1)) & mhi1)) & rvU1)
                        | ((((W ^ __funnelshift_l(lD1, cD1, 1)) & mlo1)
                          | ((W ^ __funnelshift_r(cD1, rD1, 1)) & mhi1)) & rvD1);
            res = make_uint2(h1, h2);
        } else if (sub == 1) {
            unsigned cU1 = M[sr - 1][w1 + 1], lU1 = M[sr - 1][w1], rU1 = M[sr - 1][w1 + 2];
            unsigned cD1 = M[sr + 1][w1 + 1], lD1 = M[sr + 1][w1], rD1 = M[sr + 1][w1 + 2];
            unsigned cU2 = M[sr - 2][w1 + 1], lU2 = M[sr - 2][w1], rU2 = M[sr - 2][w1 + 2];
            unsigned cD2 = M[sr + 2][w1 + 1], lD2 = M[sr + 2][w1], rD2 = M[sr + 2][w1 + 2];
            // s=4: (0,+-2), (+-2,0)
            unsigned h4 = ((W ^ __funnelshift_l(l0, W, 2)) & mlo2)
                        | ((W ^ __funnelshift_r(W, r0, 2)) & mhi2)
                        | ((W ^ cU2) & rvU2) | ((W ^ cD2) & rvD2);
            // s=5: (+-1,+-2), (+-2,+-1)
            unsigned h5 = ((((W ^ __funnelshift_l(lU1, cU1, 2)) & mlo2)
                          | ((W ^ __funnelshift_r(cU1, rU1, 2)) & mhi2)) & rvU1)
                        | ((((W ^ __funnelshift_l(lD1, cD1, 2)) & mlo2)
                          | ((W ^ __funnelshift_r(cD1, rD1, 2)) & mhi2)) & rvD1)
                        | ((((W ^ __funnelshift_l(lU2, cU2, 1)) & mlo1)
                          | ((W ^ __funnelshift_r(cU2, rU2, 1)) & mhi1)) & rvU2)
                        | ((((W ^ __funnelshift_l(lD2, cD2, 1)) & mlo1)
                          | ((W ^ __funnelshift_r(cD2, rD2, 1)) & mhi1)) & rvD2);
            res = make_uint2(h4, h5);
        } else if (sub == 2) {
            unsigned cU2 = M[sr - 2][w1 + 1], lU2 = M[sr - 2][w1], rU2 = M[sr - 2][w1 + 2];
            unsigned cD2 = M[sr + 2][w1 + 1], lD2 = M[sr + 2][w1], rD2 = M[sr + 2][w1 + 2];
            unsigned cU3 = M[sr - 3][w1 + 1], cD3 = M[sr + 3][w1 + 1];
            // s=8: (+-2,+-2)
            unsigned h8 = ((((W ^ __funnelshift_l(lU2, cU2, 2)) & mlo2)
                          | ((W ^ __funnelshift_r(cU2, rU2, 2)) & mhi2)) & rvU2)
                        | ((((W ^ __funnelshift_l(lD2, cD2, 2)) & mlo2)
                          | ((W ^ __funnelshift_r(cD2, rD2, 2)) & mhi2)) & rvD2);
            // s=9: (0,+-3), (+-3,0)
            unsigned h9 = ((W ^ __funnelshift_l(l0, W, 3)) & mlo3)
                        | ((W ^ __funnelshift_r(W, r0, 3)) & mhi3)
                        | ((W ^ cU3) & rvU3) | ((W ^ cD3) & rvD3);
            res = make_uint2(h8, h9);
        } else {
            unsigned cU1 = M[sr - 1][w1 + 1], lU1 = M[sr - 1][w1], rU1 = M[sr - 1][w1 + 2];
            unsigned cD1 = M[sr + 1][w1 + 1], lD1 = M[sr + 1][w1], rD1 = M[sr + 1][w1 + 2];
            unsigned cU2 = M[sr - 2][w1 + 1], lU2 = M[sr - 2][w1], rU2 = M[sr - 2][w1 + 2];
            unsigned cD2 = M[sr + 2][w1 + 1], lD2 = M[sr + 2][w1], rD2 = M[sr + 2][w1 + 2];
            unsigned cU3 = M[sr - 3][w1 + 1], lU3 = M[sr - 3][w1], rU3 = M[sr - 3][w1 + 2];
            unsigned cD3 = M[sr + 3][w1 + 1], lD3 = M[sr + 3][w1], rD3 = M[sr + 3][w1 + 2];
            // s=10: (+-1,+-3), (+-3,+-1)
            unsigned h10 = ((((W ^ __funnelshift_l(lU1, cU1, 3)) & mlo3)
                           | ((W ^ __funnelshift_r(cU1, rU1, 3)) & mhi3)) & rvU1)
                         | ((((W ^ __funnelshift_l(lD1, cD1, 3)) & mlo3)
                           | ((W ^ __funnelshift_r(cD1, rD1, 3)) & mhi3)) & rvD1)
                         | ((((W ^ __funnelshift_l(lU3, cU3, 1)) & mlo1)
                           | ((W ^ __funnelshift_r(cU3, rU3, 1)) & mhi1)) & rvU3)
                         | ((((W ^ __funnelshift_l(lD3, cD3, 1)) & mlo1)
                           | ((W ^ __funnelshift_r(cD3, rD3, 1)) & mhi1)) & rvD3);
            // s=13: (+-2,+-3), (+-3,+-2)
            unsigned h13 = ((((W ^ __funnelshift_l(lU2, cU2, 3)) & mlo3)
                           | ((W ^ __funnelshift_r(cU2, rU2, 3)) & mhi3)) & rvU2)
                         | ((((W ^ __funnelshift_l(lD2, cD2, 3)) & mlo3)
                           | ((W ^ __funnelshift_r(cD2, rD2, 3)) & mhi3)) & rvD2)
                         | ((((W ^ __funnelshift_l(lU3, cU3, 2)) & mlo2)
                           | ((W ^ __funnelshift_r(cU3, rU3, 2)) & mhi2)) & rvU3)
                         | ((((W ^ __funnelshift_l(lD3, cD3, 2)) & mlo2)
                           | ((W ^ __funnelshift_r(cD3, rD3, 2)) & mhi2)) & rvD3);
            res = make_uint2(h10, h13);
        }
        SL[f1][rr][w1][sub] = res;
    }
    __syncthreads();

    // ---------------- Phase 2: warp = (row, half), lane = pixel ----------------
    int row  = warp >> 1;           // 0..3
    int half = warp & 1;            // word group
    int i2   = band * BAND + row;
    float acc = 0.0f;
    unsigned fb = 0u;               // fallback events: bit = wq*2 + side
#pragma unroll
    for (int wq = 0; wq < 4; ++wq) {
        int ww = half * 4 + wq;
        float w = w_sh[row][ww * 32 + lane];
        const uint4* qp = (const uint4*)&SL[0][row][ww][0];
        const uint4* qt = (const uint4*)&SL[1][row][ww][0];
        uint4 A = qp[0], B = qp[1];
        uint4 C = qt[0], D = qt[1];
        unsigned vp = ((A.x >> lane) & 1u)        | (((A.y >> lane) & 1u) << 1)
                    | (((A.z >> lane) & 1u) << 2) | (((A.w >> lane) & 1u) << 3)
                    | (((B.x >> lane) & 1u) << 4) | (((B.y >> lane) & 1u) << 5)
                    | (((B.z >> lane) & 1u) << 6) | (((B.w >> lane) & 1u) << 7);
        unsigned vt = ((C.x >> lane) & 1u)        | (((C.y >> lane) & 1u) << 1)
                    | (((C.z >> lane) & 1u) << 2) | (((C.w >> lane) & 1u) << 3)
                    | (((D.x >> lane) & 1u) << 4) | (((D.y >> lane) & 1u) << 5)
                    | (((D.z >> lane) & 1u) << 6) | (((D.w >> lane) & 1u) << 7);
        int sp = vp ? (int)((SCALE_LUT >> ((__ffs(vp) - 1) * 4)) & 0xFu) : 0;
        int st = vt ? (int)((SCALE_LUT >> ((__ffs(vt) - 1) * 4)) & 0xFu) : 0;
        fb |= (vp == 0u ? 1u : 0u) << (wq * 2);
        fb |= (vt == 0u ? 2u : 0u) << (wq * 2);
        acc += w * (float)(sp + st);
    }
    // exact fallback (prob ~1e-4 of ANY event in this input)
    while (fb) {
        int e = __ffs(fb) - 1; fb &= fb - 1;
        int side = e & 1, wq = e >> 1;
        int col = (half * 4 + wq) * 32 + lane;
        const float* ib = side ? tbase : pbase;
        bool cls = ib[(size_t)i2 * WW + col] > 0.5f;
        acc += w_sh[row][col] * slow_scan(ib, i2, col, cls);
    }

    // reduce: warp -> block
#pragma unroll
    for (int o = 16; o > 0; o >>= 1) acc += __shfl_xor_sync(0xFFFFFFFFu, acc, o);
    if (lane == 0) sred[warp] = acc;
    __syncthreads();

    // block partial -> global accumulator; last block finalizes + resets
    if (tid == 0) {
        float sum = 0.0f;
#pragma unroll
        for (int k = 0; k < 8; ++k) sum += sred[k];
        atomicAdd(&g_accum, sum);
        __threadfence();
        unsigned prev = atomicAdd(&g_done, 1u);
        if (prev == NBLK - 1) {
            float tot = *(volatile float*)&g_accum;
            *out = tot * (1.0f / (float)NPIX);
            *(volatile float*)&g_accum = 0.0f;      // reset for next graph replay
            *(volatile unsigned*)&g_done = 0u;
            __threadfence();
        }
    }
}

extern "C" void kernel_launch(void* const* d_in, const int* in_sizes, int n_in,
                              void* d_out, int out_size) {
    const float* pred   = (const float*)d_in[0];
    const float* target = (const float*)d_in[1];
    float* out = (float*)d_out;

    hd_loss_kernel<<<dim3(64, 8), 256>>>(pred, target, out);
}

// round 10
// speedup vs baseline: 1.2007x; 1.2007x over previous
#include <cuda_runtime.h>

#define HH 256
#define WW 256
#define NW 8                 // 256 cols / 32
#define NPIX (8 * HH * WW)   // mean denominator
#define NBLK 512             // 64 bands x 8 batch
#define BAND 4               // core rows per block
#define WROWS 10             // window rows = BAND + 2*3

__device__ float    g_accum = 0.0f;
__device__ unsigned g_done  = 0u;

// ---------------------------------------------------------------------------
// Exact fallback: expanding float-based scan for nearest opposite-class pixel.
// Reached only when no opposite pixel lies within r^2 <= 13 (prob ~1e-4 of
// ANY event in this input). Exact for all inputs; 1e20 if none exists.
// ---------------------------------------------------------------------------
__device__ __noinline__ float slow_scan(const float* __restrict__ im, int i, int j, bool cls) {
    float best = 1e20f;
    for (int dd = 0; dd < HH; ++dd) {
        float dd2 = (float)(dd * dd);
        if (dd2 >= best) break;
#pragma unroll 1
        for (int s2 = 0; s2 < 2; ++s2) {
            if (s2 && dd == 0) continue;
            int r = s2 ? i - dd : i + dd;
            if (r < 0 || r >= HH) continue;
            const float* row = im + (size_t)r * WW;
            for (int dj = 0; dj < WW; ++dj) {
                float tot = dd2 + (float)(dj * dj);
                if (tot >= best) break;
                int c1 = j + dj, c2 = j - dj;
                if (c1 < WW && ((row[c1] > 0.5f) != cls)) { best = tot; break; }
                if (dj && c2 >= 0 && ((row[c2] > 0.5f) != cls)) { best = tot; break; }
            }
        }
    }
    return best;
}

// ---------------------------------------------------------------------------
// Single fused kernel (R8 structure + front-batched phase-0 loads).
// Block = (band of 4 rows, batch), 256 threads (8 warps).
// Phase 0: warp = word column; k = window row. ALL 20 LDGs issued first
//          (MLP=20), then ballots/stores on landed data.
// Phase 1: threads 0..63 = (image, row, word) -> 4 bit-planes, gated levels
//          r^2 in {1,2,4,5,8} + {9,10,13}. s = p0+2p1+4p2+8p3.
// Phase 2: warp = (row, word-half), lane = pixel: acc += w*(s_pred+s_target);
//          s==0 -> exact slow_scan.
// Output: last-block finalize (idempotent across graph replays).
// ---------------------------------------------------------------------------
__global__ void __launch_bounds__(256) hd_loss_kernel(const float* __restrict__ pred,
                                                      const float* __restrict__ target,
                                                      float* __restrict__ out) {
    int band = blockIdx.x;          // 0..63
    int b    = blockIdx.y;          // 0..7
    int tid  = threadIdx.x;         // 0..255
    int lane = tid & 31;
    int warp = tid >> 5;            // 0..7

    __shared__ unsigned SM[2][WROWS][10];   // window rows band*4-3..+6, pad cols 0,9
    __shared__ uint4    SP[2][BAND][NW];    // bit-planes p0..p3
    __shared__ float    w_sh[BAND][WW];     // (p-t)^2 core rows
    __shared__ float    sred[8];

    const float* pbase = pred   + (size_t)b * HH * WW;
    const float* tbase = target + (size_t)b * HH * WW;

    // zero pads: 2 img x 10 rows x 2 pad cols = 40 slots
    if (tid < 40) {
        int f = tid / 20, rr = (tid >> 1) % 10, cc = tid & 1;
        SM[f][rr][cc * 9] = 0u;
    }

    // ---------------- Phase 0: front-batched loads, then ballots ----------------
    // warp = fixed word column; k = window row 0..9 (slot = warp + 8k).
    {
        int col = warp * 32 + lane;
        float vp[WROWS], vt[WROWS];
#pragma unroll
        for (int k = 0; k < WROWS; ++k) {        // 20 independent LDGs, MLP-batched
            int gi = band * BAND - 3 + k;
            gi = gi < 0 ? 0 : (gi > HH - 1 ? HH - 1 : gi);  // clamp; rv masks fix validity
            vp[k] = pbase[(size_t)gi * WW + col];
            vt[k] = tbase[(size_t)gi * WW + col];
        }
#pragma unroll
        for (int k = 0; k < WROWS; ++k) {
            unsigned mp = __ballot_sync(0xFFFFFFFFu, vp[k] > 0.5f);
            unsigned mt = __ballot_sync(0xFFFFFFFFu, vt[k] > 0.5f);
            if (lane == 0) {
                SM[0][k][warp + 1] = mp;
                SM[1][k][warp + 1] = mt;
            }
            if (k >= 3 && k < 3 + BAND) {
                float d = vp[k] - vt[k];
                w_sh[k - 3][col] = d * d;
            }
        }
    }
    __syncthreads();

    // ---------------- Phase 1: one word-task per thread (64 tasks) ----------------
    if (tid < 64) {
        int f1 = tid >> 5;          // 0 = pred, 1 = target
        int rr = (tid >> 3) & 3;    // core row in band
        int w1 = tid & 7;           // word
        int i1 = band * BAND + rr;
        int sr = rr + 3;
        const unsigned (*M)[10] = SM[f1];

        unsigned W   = M[sr][w1 + 1];
        unsigned l0  = M[sr][w1],         r0  = M[sr][w1 + 2];
        unsigned cU1 = M[sr - 1][w1 + 1], lU1 = M[sr - 1][w1], rU1 = M[sr - 1][w1 + 2];
        unsigned cD1 = M[sr + 1][w1 + 1], lD1 = M[sr + 1][w1], rD1 = M[sr + 1][w1 + 2];

        unsigned mlo1 = (w1 == 0) ? 0xFFFFFFFEu : 0xFFFFFFFFu;
        unsigned mlo2 = (w1 == 0) ? 0xFFFFFFFCu : 0xFFFFFFFFu;
        unsigned mlo3 = (w1 == 0) ? 0xFFFFFFF8u : 0xFFFFFFFFu;
        unsigned mhi1 = (w1 == 7) ? 0x7FFFFFFFu : 0xFFFFFFFFu;
        unsigned mhi2 = (w1 == 7) ? 0x3FFFFFFFu : 0xFFFFFFFFu;
        unsigned mhi3 = (w1 == 7) ? 0x1FFFFFFFu : 0xFFFFFFFFu;
        unsigned rvU1 = (i1 >= 1)      ? 0xFFFFFFFFu : 0u;
        unsigned rvD1 = (i1 <= HH - 2) ? 0xFFFFFFFFu : 0u;
        unsigned rvU2 = (i1 >= 2)      ? 0xFFFFFFFFu : 0u;
        unsigned rvD2 = (i1 <= HH - 3) ? 0xFFFFFFFFu : 0u;
        unsigned rvU3 = (i1 >= 3)      ? 0xFFFFFFFFu : 0u;
        unsigned rvD3 = (i1 <= HH - 4) ? 0xFFFFFFFFu : 0u;

        // s=1: (0,+-1), (+-1,0)
        unsigned h1 = ((W ^ __funnelshift_l(l0, W, 1)) & mlo1)
                    | ((W ^ __funnelshift_r(W, r0, 1)) & mhi1)
                    | ((W ^ cU1) & rvU1) | ((W ^ cD1) & rvD1);
        // s=2: (+-1,+-1)
        unsigned h2 = (((((W ^ __funnelshift_l(lU1, cU1, 1)) & mlo1)
                       | ((W ^ __funnelshift_r(cU1, rU1, 1)) & mhi1)) & rvU1)
                     | ((((W ^ __funnelshift_l(lD1, cD1, 1)) & mlo1)
                       | ((W ^ __funnelshift_r(cD1, rD1, 1)) & mhi1)) & rvD1)) & ~h1;
        unsigned p0 = h1, p1 = h2, p2 = 0u, p3 = 0u;
        unsigned U = ~(h1 | h2);
        if (U) {
            unsigned cU2 = M[sr - 2][w1 + 1], lU2 = M[sr - 2][w1], rU2 = M[sr - 2][w1 + 2];
            unsigned cD2 = M[sr + 2][w1 + 1], lD2 = M[sr + 2][w1], rD2 = M[sr + 2][w1 + 2];
            // s=4: (0,+-2), (+-2,0)
            unsigned h4 = (((W ^ __funnelshift_l(l0, W, 2)) & mlo2)
                         | ((W ^ __funnelshift_r(W, r0, 2)) & mhi2)
                         | ((W ^ cU2) & rvU2) | ((W ^ cD2) & rvD2)) & U;
            p2 = h4; U &= ~h4;
            // s=5: (+-1,+-2), (+-2,+-1)
            unsigned h5 = (((((W ^ __funnelshift_l(lU1, cU1, 2)) & mlo2)
                           | ((W ^ __funnelshift_r(cU1, rU1, 2)) & mhi2)) & rvU1)
                         | ((((W ^ __funnelshift_l(lD1, cD1, 2)) & mlo2)
                           | ((W ^ __funnelshift_r(cD1, rD1, 2)) & mhi2)) & rvD1)
                         | ((((W ^ __funnelshift_l(lU2, cU2, 1)) & mlo1)
                           | ((W ^ __funnelshift_r(cU2, rU2, 1)) & mhi1)) & rvU2)
                         | ((((W ^ __funnelshift_l(lD2, cD2, 1)) & mlo1)
                           | ((W ^ __funnelshift_r(cD2, rD2, 1)) & mhi1)) & rvD2)) & U;
            p0 |= h5; p2 |= h5; U &= ~h5;
            // s=8: (+-2,+-2)
            unsigned h8 = (((((W ^ __funnelshift_l(lU2, cU2, 2)) & mlo2)
                           | ((W ^ __funnelshift_r(cU2, rU2, 2)) & mhi2)) & rvU2)
                         | ((((W ^ __funnelshift_l(lD2, cD2, 2)) & mlo2)
                           | ((W ^ __funnelshift_r(cD2, rD2, 2)) & mhi2)) & rvD2)) & U;
            p3 = h8; U &= ~h8;
            if (U) {  // essentially only border words
                unsigned cU3 = M[sr - 3][w1 + 1], lU3 = M[sr - 3][w1], rU3 = M[sr - 3][w1 + 2];
                unsigned cD3 = M[sr + 3][w1 + 1], lD3 = M[sr + 3][w1], rD3 = M[sr + 3][w1 + 2];
                // s=9: (0,+-3), (+-3,0)
                unsigned h9 = (((W ^ __funnelshift_l(l0, W, 3)) & mlo3)
                             | ((W ^ __funnelshift_r(W, r0, 3)) & mhi3)
                             | ((W ^ cU3) & rvU3) | ((W ^ cD3) & rvD3)) & U;
                p0 |= h9; p3 |= h9; U &= ~h9;
                // s=10: (+-1,+-3), (+-3,+-1)
                unsigned h10 = (((((W ^ __funnelshift_l(lU1, cU1, 3)) & mlo3)
                                | ((W ^ __funnelshift_r(cU1, rU1, 3)) & mhi3)) & rvU1)
                              | ((((W ^ __funnelshift_l(lD1, cD1, 3)) & mlo3)
                                | ((W ^ __funnelshift_r(cD1, rD1, 3)) & mhi3)) & rvD1)
                              | ((((W ^ __funnelshift_l(lU3, cU3, 1)) & mlo1)
                                | ((W ^ __funnelshift_r(cU3, rU3, 1)) & mhi1)) & rvU3)
                              | ((((W ^ __funnelshift_l(lD3, cD3, 1)) & mlo1)
                                | ((W ^ __funnelshift_r(cD3, rD3, 1)) & mhi1)) & rvD3)) & U;
                p1 |= h10; p3 |= h10; U &= ~h10;
                // s=13: (+-2,+-3), (+-3,+-2)
                unsigned h13 = (((((W ^ __funnelshift_l(lU2, cU2, 3)) & mlo3)
                                | ((W ^ __funnelshift_r(cU2, rU2, 3)) & mhi3)) & rvU2)
                              | ((((W ^ __funnelshift_l(lD2, cD2, 3)) & mlo3)
                                | ((W ^ __funnelshift_r(cD2, rD2, 3)) & mhi3)) & rvD2)
                              | ((((W ^ __funnelshift_l(lU3, cU3, 2)) & mlo2)
                                | ((W ^ __funnelshift_r(cU3, rU3, 2)) & mhi2)) & rvU3)
                              | ((((W ^ __funnelshift_l(lD3, cD3, 2)) & mlo2)
                                | ((W ^ __funnelshift_r(cD3, rD3, 2)) & mhi2)) & rvD3)) & U;
                p0 |= h13; p2 |= h13; p3 |= h13;
                // unresolved keeps all-planes-0 -> exact fallback
            }
        }
        SP[f1][rr][w1] = make_uint4(p0, p1, p2, p3);
    }
    __syncthreads();

    // ---------------- Phase 2: warp = (row, half), lane = pixel ----------------
    int row  = warp >> 1;           // 0..3
    int half = warp & 1;            // word group
    int i2   = band * BAND + row;
    float acc = 0.0f;
    unsigned fb = 0u;               // fallback events: bit = wq*2 + side
#pragma unroll
    for (int wq = 0; wq < 4; ++wq) {
        int ww = half * 4 + wq;
        float w = w_sh[row][ww * 32 + lane];
        uint4 P = SP[0][row][ww];
        uint4 Q = SP[1][row][ww];
        int sp = (int)((P.x >> lane) & 1u) | ((int)((P.y >> lane) & 1u) << 1)
               | ((int)((P.z >> lane) & 1u) << 2) | ((int)((P.w >> lane) & 1u) << 3);
        int st = (int)((Q.x >> lane) & 1u) | ((int)((Q.y >> lane) & 1u) << 1)
               | ((int)((Q.z >> lane) & 1u) << 2) | ((int)((Q.w >> lane) & 1u) << 3);
        fb |= (sp == 0 ? 1u : 0u) << (wq * 2);
        fb |= (st == 0 ? 2u : 0u) << (wq * 2);
        acc += w * (float)(sp + st);
    }
    // exact fallback (prob ~1e-4 of ANY event in this input)
    while (fb) {
        int e = __ffs(fb) - 1; fb &= fb - 1;
        int side = e & 1, wq = e >> 1;
        int col = (half * 4 + wq) * 32 + lane;
        const float* ib = side ? tbase : pbase;
        bool cls = ib[(size_t)i2 * WW + col] > 0.5f;
        acc += w_sh[row][col] * slow_scan(ib, i2, col, cls);
    }

    // reduce: warp -> block
#pragma unroll
    for (int o = 16; o > 0; o >>= 1) acc += __shfl_xor_sync(0xFFFFFFFFu, acc, o);
    if (lane == 0) sred[warp] = acc;
    __syncthreads();

    // block partial -> global accumulator; last block finalizes + resets
    if (tid == 0) {
        float sum = 0.0f;
#pragma unroll
        for (int k = 0; k < 8; ++k) sum += sred[k];
        atomicAdd(&g_accum, sum);
        __threadfence();
        unsigned prev = atomicAdd(&g_done, 1u);
        if (prev == NBLK - 1) {
            float tot = *(volatile float*)&g_accum;
            *out = tot * (1.0f / (float)NPIX);
            *(volatile float*)&g_accum = 0.0f;      // reset for next graph replay
            *(volatile unsigned*)&g_done = 0u;
            __threadfence();
        }
    }
}

extern "C" void kernel_launch(void* const* d_in, const int* in_sizes, int n_in,
                              void* d_out, int out_size) {
    const float* pred   = (const float*)d_in[0];
    const float* target = (const float*)d_in[1];
    float* out = (float*)d_out;

    hd_loss_kernel<<<dim3(64, 8), 256>>>(pred, target, out);
}